// round 1
// baseline (speedup 1.0000x reference)
#include <cuda_runtime.h>
#include <cstdint>

// Problem shape (fixed by the reference): B=4, N=M=8192, D=3, fp32.
#define BATCH     4
#define NPTS      8192
#define YTILE     2048          // points per smem tile
#define PAIRS     (YTILE / 2)   // packed y-pairs per tile
#define THREADS   128
#define IX        2             // x points per thread
#define XPERCTA   (THREADS * IX)   // 256
#define XCHUNKS   (NPTS / XPERCTA) // 32
#define YCHUNKS   (NPTS / YTILE)   // 4
#define GRID      (2 * BATCH * XCHUNKS * YCHUNKS)  // 1024
#define TOTMIN    (2 * BATCH * NPTS)               // 65536

// Cross-CTA min scratch: uint bit-pattern of non-negative fp32 distances.
// (uint compare == float compare for non-negative floats.)
__device__ unsigned int g_min[TOTMIN];

// ---------------- packed f32x2 helpers (Blackwell-only) ----------------
__device__ __forceinline__ unsigned long long pk_ff(float lo, float hi) {
    unsigned long long r;
    asm("mov.b64 %0, {%1,%2};" : "=l"(r) : "f"(lo), "f"(hi));
    return r;
}
__device__ __forceinline__ unsigned long long pk_uu(unsigned int lo, unsigned int hi) {
    unsigned long long r;
    asm("mov.b64 %0, {%1,%2};" : "=l"(r) : "r"(lo), "r"(hi));
    return r;
}
__device__ __forceinline__ unsigned long long fma2(unsigned long long a,
                                                   unsigned long long b,
                                                   unsigned long long c) {
    unsigned long long d;
    asm("fma.rn.f32x2 %0, %1, %2, %3;" : "=l"(d) : "l"(a), "l"(b), "l"(c));
    return d;
}
__device__ __forceinline__ void unpk(unsigned long long v, float& lo, float& hi) {
    asm("mov.b64 {%0,%1}, %2;" : "=f"(lo), "=f"(hi) : "l"(v));
}

// ---------------- init: g_min <- +inf ----------------
__global__ void chamfer_init_kernel() {
    int i = blockIdx.x * blockDim.x + threadIdx.x;
    if (i < TOTMIN) g_min[i] = 0x7f800000u;  // +inf bits
}

// ---------------- main: per-point min over a y-chunk ----------------
__global__ void __launch_bounds__(THREADS)
chamfer_min_kernel(const float* __restrict__ x, const float* __restrict__ y) {
    // smem layout per pair p: [y0a y0b y1a y1b y2a y2b nna nnb]  (8 floats, 32B)
    __shared__ float sh[YTILE * 4];

    const int cta = blockIdx.x;
    const int yc  = cta & (YCHUNKS - 1);
    const int xc  = (cta >> 2) & (XCHUNKS - 1);
    const int b   = (cta >> 7) & (BATCH - 1);
    const int dir = (cta >> 9) & 1;

    const float* src = dir ? y : x;  // points we minimize FOR
    const float* dst = dir ? x : y;  // points we search over

    // ---- cooperative fill of the y tile (with precomputed ||y||^2) ----
    const float* dbase = dst + ((size_t)b * NPTS + (size_t)yc * YTILE) * 3;
    for (int m = threadIdx.x; m < YTILE; m += THREADS) {
        float a0 = dbase[m * 3 + 0];
        float a1 = dbase[m * 3 + 1];
        float a2 = dbase[m * 3 + 2];
        float nn = fmaf(a0, a0, fmaf(a1, a1, a2 * a2));
        int p = m >> 1, h = m & 1;
        float* s = sh + p * 8 + h;
        s[0] = a0; s[2] = a1; s[4] = a2; s[6] = nn;
    }
    __syncthreads();

    // ---- per-thread x points: coefficients (-2x) broadcast into f32x2 ----
    const float* sbase = src + ((size_t)b * NPTS + (size_t)xc * XPERCTA) * 3;
    unsigned long long C0[IX], C1[IX], C2[IX];
    float x2v[IX];
    float mnlo[IX], mnhi[IX];
#pragma unroll
    for (int i = 0; i < IX; i++) {
        int xi = threadIdx.x + i * THREADS;
        float a0 = sbase[xi * 3 + 0];
        float a1 = sbase[xi * 3 + 1];
        float a2 = sbase[xi * 3 + 2];
        x2v[i] = fmaf(a0, a0, fmaf(a1, a1, a2 * a2));
        C0[i] = pk_ff(-2.0f * a0, -2.0f * a0);
        C1[i] = pk_ff(-2.0f * a1, -2.0f * a1);
        C2[i] = pk_ff(-2.0f * a2, -2.0f * a2);
        mnlo[i] = 3.0e38f;
        mnhi[i] = 3.0e38f;
    }

    // ---- inner loop: 2 LDS.128 + 6 FMA2 + 4 FMNMX per warp iteration ----
    const uint4* shp = (const uint4*)sh;
#pragma unroll 4
    for (int p = 0; p < PAIRS; ++p) {
        uint4 va = shp[2 * p + 0];   // y0 pair, y1 pair
        uint4 vb = shp[2 * p + 1];   // y2 pair, nn pair
        unsigned long long y0 = pk_uu(va.x, va.y);
        unsigned long long y1 = pk_uu(va.z, va.w);
        unsigned long long y2 = pk_uu(vb.x, vb.y);
        unsigned long long nn = pk_uu(vb.z, vb.w);
#pragma unroll
        for (int i = 0; i < IX; i++) {
            unsigned long long acc = fma2(C0[i], y0, nn);
            acc = fma2(C1[i], y1, acc);
            acc = fma2(C2[i], y2, acc);
            float lo, hi;
            unpk(acc, lo, hi);
            mnlo[i] = fminf(mnlo[i], lo);
            mnhi[i] = fminf(mnhi[i], hi);
        }
    }

    // ---- combine halves, add ||x||^2, clamp, cross-CTA atomicMin ----
#pragma unroll
    for (int i = 0; i < IX; i++) {
        float m = fminf(mnlo[i], mnhi[i]);
        float dist = fmaxf(x2v[i] + m, 0.0f);   // non-negative by construction
        int idx = (dir * BATCH + b) * NPTS + xc * XPERCTA + i * THREADS + threadIdx.x;
        atomicMin(&g_min[idx], __float_as_uint(dist));
    }
}

// ---------------- final: deterministic sum + scale ----------------
__global__ void chamfer_sum_kernel(float* __restrict__ out) {
    __shared__ float red[1024];
    float s = 0.0f;
    for (int i = threadIdx.x; i < TOTMIN; i += 1024)
        s += __uint_as_float(g_min[i]);
    red[threadIdx.x] = s;
    __syncthreads();
    for (int k = 512; k > 0; k >>= 1) {
        if (threadIdx.x < k) red[threadIdx.x] += red[threadIdx.x + k];
        __syncthreads();
    }
    if (threadIdx.x == 0)
        out[0] = red[0] * (1.0f / (float)(BATCH * NPTS));
}

extern "C" void kernel_launch(void* const* d_in, const int* in_sizes, int n_in,
                              void* d_out, int out_size) {
    const float* x = (const float*)d_in[0];
    const float* y = (const float*)d_in[1];
    float* out = (float*)d_out;
    (void)in_sizes; (void)n_in; (void)out_size;

    chamfer_init_kernel<<<(TOTMIN + 1023) / 1024, 1024>>>();
    chamfer_min_kernel<<<GRID, THREADS>>>(x, y);
    chamfer_sum_kernel<<<1, 1024>>>(out);
}

// round 2
// speedup vs baseline: 1.0624x; 1.0624x over previous
#include <cuda_runtime.h>
#include <cstdint>

// Problem shape (fixed by the reference): B=4, N=M=8192, D=3, fp32.
#define BATCH     4
#define NPTS      8192
#define YTILE     2048          // points per smem tile
#define PAIRS     (YTILE / 2)   // packed y-pairs per tile
#define THREADS   128
#define IX        4             // x points per thread
#define XPERCTA   (THREADS * IX)   // 512
#define XCHUNKS   (NPTS / XPERCTA) // 16
#define YCHUNKS   (NPTS / YTILE)   // 4
#define GRID      (2 * BATCH * XCHUNKS * YCHUNKS)  // 512
#define TOTMIN    (2 * BATCH * NPTS)               // 65536
#define INF_BITS  0x7f800000u

// Cross-CTA combine scratch. Zero-initialized at module load.
// Stores key = INF_BITS - float_bits(dist); atomicMax(key) == min(dist).
// key >= 1 for any valid non-negative dist, so 0 means "empty".
// The sum kernel re-zeros it, making each graph replay self-contained.
__device__ unsigned int g_acc[TOTMIN];

__device__ __forceinline__ unsigned long long pk_ff(float lo, float hi) {
    unsigned long long r;
    asm("mov.b64 %0, {%1,%2};" : "=l"(r) : "f"(lo), "f"(hi));
    return r;
}

// One packed candidate evaluation: acc = nn - 2*x.y (2 y-points at once),
// folded straight into the running per-x minima. Single asm block so ptxas
// can coalesce the pair-split mov into register aliasing.
__device__ __forceinline__ void step(float& mlo, float& mhi,
    unsigned long long c0, unsigned long long c1, unsigned long long c2,
    unsigned long long y0, unsigned long long y1, unsigned long long y2,
    unsigned long long nn)
{
    asm("{\n\t"
        ".reg .b64 t;\n\t"
        ".reg .f32 lo, hi;\n\t"
        "fma.rn.f32x2 t, %2, %5, %8;\n\t"
        "fma.rn.f32x2 t, %3, %6, t;\n\t"
        "fma.rn.f32x2 t, %4, %7, t;\n\t"
        "mov.b64 {lo, hi}, t;\n\t"
        "min.f32 %0, %0, lo;\n\t"
        "min.f32 %1, %1, hi;\n\t"
        "}"
        : "+f"(mlo), "+f"(mhi)
        : "l"(c0), "l"(c1), "l"(c2), "l"(y0), "l"(y1), "l"(y2), "l"(nn));
}

__global__ void __launch_bounds__(THREADS)
chamfer_min_kernel(const float* __restrict__ x, const float* __restrict__ y) {
    // smem layout per pair p (32 bytes): [y0a y0b | y1a y1b | y2a y2b | nna nnb]
    __shared__ __align__(16) float sh[YTILE * 4];

    const int cta = blockIdx.x;
    const int yc  = cta & (YCHUNKS - 1);
    const int xc  = (cta >> 2) & (XCHUNKS - 1);
    const int b   = (cta >> 6) & (BATCH - 1);
    const int dir = (cta >> 8) & 1;

    const float* src = dir ? y : x;  // points we minimize FOR
    const float* dst = dir ? x : y;  // points we search over

    // ---- cooperative fill of the y tile (with precomputed ||y||^2) ----
    const float* dbase = dst + ((size_t)b * NPTS + (size_t)yc * YTILE) * 3;
    for (int m = threadIdx.x; m < YTILE; m += THREADS) {
        float a0 = dbase[m * 3 + 0];
        float a1 = dbase[m * 3 + 1];
        float a2 = dbase[m * 3 + 2];
        float nn = fmaf(a0, a0, fmaf(a1, a1, a2 * a2));
        int p = m >> 1, h = m & 1;
        float* s = sh + p * 8 + h;
        s[0] = a0; s[2] = a1; s[4] = a2; s[6] = nn;
    }
    __syncthreads();

    // ---- per-thread x points: coefficients (-2x) broadcast into f32x2 ----
    const float* sbase = src + ((size_t)b * NPTS + (size_t)xc * XPERCTA) * 3;
    unsigned long long C0[IX], C1[IX], C2[IX];
    float x2v[IX];
    float mnlo[IX], mnhi[IX];
#pragma unroll
    for (int i = 0; i < IX; i++) {
        int xi = threadIdx.x + i * THREADS;
        float a0 = sbase[xi * 3 + 0];
        float a1 = sbase[xi * 3 + 1];
        float a2 = sbase[xi * 3 + 2];
        x2v[i] = fmaf(a0, a0, fmaf(a1, a1, a2 * a2));
        C0[i] = pk_ff(-2.0f * a0, -2.0f * a0);
        C1[i] = pk_ff(-2.0f * a1, -2.0f * a1);
        C2[i] = pk_ff(-2.0f * a2, -2.0f * a2);
        mnlo[i] = 3.0e38f;
        mnhi[i] = 3.0e38f;
    }

    // ---- inner loop: 2 LDS.128 + 12 FMA2 + 8 FMNMX per warp iteration ----
    const ulonglong2* shp = (const ulonglong2*)sh;
#pragma unroll 4
    for (int p = 0; p < PAIRS; ++p) {
        ulonglong2 va = shp[2 * p + 0];  // y0 pair, y1 pair
        ulonglong2 vb = shp[2 * p + 1];  // y2 pair, nn pair
#pragma unroll
        for (int i = 0; i < IX; i++)
            step(mnlo[i], mnhi[i], C0[i], C1[i], C2[i], va.x, va.y, vb.x, vb.y);
    }

    // ---- combine halves, add ||x||^2, clamp, cross-CTA combine ----
#pragma unroll
    for (int i = 0; i < IX; i++) {
        float m = fminf(mnlo[i], mnhi[i]);
        float dist = fmaxf(x2v[i] + m, 0.0f);   // non-negative by construction
        int idx = (dir * BATCH + b) * NPTS + xc * XPERCTA + i * THREADS + threadIdx.x;
        atomicMax(&g_acc[idx], INF_BITS - __float_as_uint(dist));
    }
}

// ---------------- final: deterministic sum + scale + re-zero ----------------
__global__ void chamfer_sum_kernel(float* __restrict__ out) {
    __shared__ float red[1024];
    uint4* gp = (uint4*)g_acc;
    float s = 0.0f;
    for (int i = threadIdx.x; i < TOTMIN / 4; i += 1024) {
        uint4 v = gp[i];
        s += __uint_as_float(INF_BITS - v.x);
        s += __uint_as_float(INF_BITS - v.y);
        s += __uint_as_float(INF_BITS - v.z);
        s += __uint_as_float(INF_BITS - v.w);
        gp[i] = make_uint4(0u, 0u, 0u, 0u);   // reset for next replay
    }
    red[threadIdx.x] = s;
    __syncthreads();
    for (int k = 512; k > 0; k >>= 1) {
        if (threadIdx.x < k) red[threadIdx.x] += red[threadIdx.x + k];
        __syncthreads();
    }
    if (threadIdx.x == 0)
        out[0] = red[0] * (1.0f / (float)(BATCH * NPTS));
}

extern "C" void kernel_launch(void* const* d_in, const int* in_sizes, int n_in,
                              void* d_out, int out_size) {
    const float* x = (const float*)d_in[0];
    const float* y = (const float*)d_in[1];
    float* out = (float*)d_out;
    (void)in_sizes; (void)n_in; (void)out_size;

    chamfer_min_kernel<<<GRID, THREADS>>>(x, y);
    chamfer_sum_kernel<<<1, 1024>>>(out);
}